// round 15
// baseline (speedup 1.0000x reference)
#include <cuda_runtime.h>
#include <cuda_fp16.h>

#define TSTEPS 30
#define EPB    64            // elements per block
#define BLOCK  128           // 2 threads per element
#define NBATCH 262144

constexpr int WTOT = 2432;   // prepped weight floats in smem (same layout sizes as R5)

typedef unsigned long long u64;
typedef unsigned int       u32;

// ---------- packed fp32x2 helpers ----------
__device__ __forceinline__ u64 ffma2(u64 a, u64 b, u64 c) {
    u64 d; asm("fma.rn.f32x2 %0, %1, %2, %3;" : "=l"(d) : "l"(a), "l"(b), "l"(c)); return d;
}
__device__ __forceinline__ u64 add2(u64 a, u64 b) {
    u64 d; asm("add.rn.f32x2 %0, %1, %2;" : "=l"(d) : "l"(a), "l"(b)); return d;
}
__device__ __forceinline__ u64 splat2(float v) {
    u64 d; asm("mov.b64 %0, {%1, %1};" : "=l"(d) : "f"(v)); return d;
}
__device__ __forceinline__ u64 pack2(float x, float y) {
    u64 d; asm("mov.b64 %0, {%1, %2};" : "=l"(d) : "f"(x), "f"(y)); return d;
}
__device__ __forceinline__ float2 unpack2(u64 v) {
    float2 r; asm("mov.b64 {%0, %1}, %2;" : "=f"(r.x), "=f"(r.y) : "l"(v)); return r;
}
__device__ __forceinline__ float tanhfast(float x){ float r; asm("tanh.approx.f32 %0, %1;" : "=f"(r) : "f"(x)); return r; }
__device__ __forceinline__ float sigt(float x){ return fmaf(0.5f, tanhfast(x), 0.5f); }  // arg pre-scaled by 0.5
__device__ __forceinline__ float xshfl(float v){ return __shfl_xor_sync(0xffffffffu, v, 1); }

__device__ __forceinline__ int comboOff(int c){ return c < 2 ? c*128 : 256 + (c-2)*272; }

union H4 { u64 u; u32 w[2]; __half2 h[2]; };
union H2 { u32 u; __half2 h; };
__device__ __forceinline__ u64 h4pack(__half2 a, __half2 b){ H4 t; t.h[0]=a; t.h[1]=b; return t.u; }
__device__ __forceinline__ u32 h2pack(float x, float y){ H2 t; t.h = __floats2half2_rn(x,y); return t.u; }

// ---- slot layout (per weight row of 16 floats, split 8/8 across the lane pair) ----
// side0 (f0-7):  r0,z0, r1,z1, r2,z2, n0,n1
// side1 (f8-15): r3,z3, r4,z4, n2,n3, n4,pad
// rz slots pre-scaled 0.5 (sig(v)=0.5+0.5*tanh(v/2)); n slots unscaled.
// PyTorch gate rows: r(u)=u, z(u)=5+u, n(u)=10+u.
__device__ __forceinline__ int slot2j(int s) {
    if (s < 6)  return (s & 1)*5 + (s >> 1);          // rz units 0..2
    if (s < 8)  return 10 + (s - 6);                  // n0,n1
    if (s < 12) return (s & 1)*5 + 3 + ((s - 8) >> 1);// rz units 3,4
    return s;                                         // 12,13,14 -> n2,n3,n4
}
__device__ __forceinline__ bool slot_rz(int s) { return (s < 6) || (s >= 8 && s < 12); }

// ---------- per-direction constants (per-thread = its 8-slot half) ----------
__device__ __forceinline__ void load_dir(const float* wbase, int D, int sideOff,
                                         u64* whhr, u64* bA, u64* bH)
{
    const float* wh = wbase + 16*D;
#pragma unroll
    for (int k = 0; k < 5; ++k) {
        const float4* row = (const float4*)(wh + k*16 + sideOff);
        float4 qa = row[0], qb = row[1];
        whhr[k*4+0] = pack2(qa.x,qa.y); whhr[k*4+1] = pack2(qa.z,qa.w);
        whhr[k*4+2] = pack2(qb.x,qb.y); whhr[k*4+3] = pack2(qb.z,qb.w);
    }
    {
        const float4* bg = (const float4*)(wbase + 16*D + 80 + sideOff);
        float4 qa = bg[0], qb = bg[1];
        bA[0] = pack2(qa.x,qa.y); bA[1] = pack2(qa.z,qa.w);
        bA[2] = pack2(qb.x,qb.y); bA[3] = pack2(qb.z,qb.w);
    }
    {
        const float4* bh = (const float4*)(wbase + 16*D + 96 + sideOff);
        float4 qa = bh[0], qb = bh[1];
        bH[0] = pack2(qa.x,qa.y); bH[1] = pack2(qa.z,qa.w);
        bH[2] = pack2(qb.x,qb.y); bH[3] = pack2(qb.z,qb.w);
    }
}

// ---------- one GRU timestep, lane-pair cooperative. h[5] full on both sides. ----------
template<int D>
__device__ __forceinline__ void step_pair(const float* __restrict__ wbase, int sideOff, int side,
                                          const u64* whhr, const u64* bA, const u64* bH,
                                          const float* xin, float* h)
{
    u64 A[4], H[4];
#pragma unroll
    for (int p = 0; p < 4; ++p) { A[p] = bA[p]; H[p] = bH[p]; }
#pragma unroll
    for (int k = 0; k < D; ++k) {                 // gi GEMV (own 8 slots)
        u64 xs = splat2(xin[k]);
        const float4* row = (const float4*)(wbase + k*16 + sideOff);
        float4 qa = row[0], qb = row[1];
        A[0] = ffma2(pack2(qa.x,qa.y), xs, A[0]);
        A[1] = ffma2(pack2(qa.z,qa.w), xs, A[1]);
        A[2] = ffma2(pack2(qb.x,qb.y), xs, A[2]);
        A[3] = ffma2(pack2(qb.z,qb.w), xs, A[3]);
    }
#pragma unroll
    for (int k = 0; k < 5; ++k) {                 // gh GEMV (register whh half)
        u64 hs = splat2(h[k]);
        H[0] = ffma2(whhr[k*4+0], hs, H[0]);
        H[1] = ffma2(whhr[k*4+1], hs, H[1]);
        H[2] = ffma2(whhr[k*4+2], hs, H[2]);
        H[3] = ffma2(whhr[k*4+3], hs, H[3]);
    }
    // rz args = gi + gh (S0..S2); n pairs use raw A/H
    float2 t0 = unpack2(add2(A[0], H[0]));
    float2 t1 = unpack2(add2(A[1], H[1]));
    float2 t2 = unpack2(add2(A[2], H[2]));
    float2 a2 = unpack2(A[2]), h2v = unpack2(H[2]);
    float2 a3 = unpack2(A[3]), h3v = unpack2(H[3]);
    // cross: side0 receives side1's (gn2, hn2)
    float gn2o = xshfl(a2.x);
    float hn2o = xshfl(h2v.x);
    // rz gates: side0 -> units 0,1,2 ; side1 -> units 3,4 (+garbage c)
    float r_a = sigt(t0.x), z_a = sigt(t0.y);
    float r_b = sigt(t1.x), z_b = sigt(t1.y);
    float r_c = sigt(t2.x), z_c = sigt(t2.y);
    // n gate sources: side0: n0=A3.x,n1=A3.y,n2=recv ; side1: n3=A2.y,n4=A3.x
    float gn_a = side ? a2.y  : a3.x;   float hn_a = side ? h2v.y : h3v.x;
    float gn_b = side ? a3.x  : a3.y;   float hn_b = side ? h3v.x : h3v.y;
    float n_a = tanhfast(fmaf(r_a, hn_a, gn_a));
    float n_b = tanhfast(fmaf(r_b, hn_b, gn_b));
    float n_c = tanhfast(fmaf(r_c, hn2o, gn2o));  // side1 garbage
    // owned h updates: side0 owns (0,1,2); side1 owns (3,4)
    float ha = side ? h[3] : h[0];
    float hb = side ? h[4] : h[1];
    float hc = h[2];
    float ua = fmaf(z_a, ha - n_a, n_a);
    float ub = fmaf(z_b, hb - n_b, n_b);
    float uc = fmaf(z_c, hc - n_c, n_c);          // side1 garbage
    // exchange -> full h on both sides
    float oa = xshfl(ua), ob = xshfl(ub), oc = xshfl(uc);
    h[0] = side ? oa : ua;
    h[1] = side ? ob : ub;
    h[2] = side ? oc : uc;
    h[3] = side ? ua : oa;
    h[4] = side ? ub : ob;
}

// fp16 triplet -> 10 floats (fwd 0..4, bwd 5..9)
__device__ __forceinline__ void cvt_in(u64 ra, u64 rb, u32 rc, float* xin)
{
    H4 a, b; H2 c; a.u = ra; b.u = rb; c.u = rc;
    float2 p0 = __half22float2(a.h[0]);
    float2 p1 = __half22float2(a.h[1]);
    float2 p2 = __half22float2(b.h[0]);
    float2 p3 = __half22float2(b.h[1]);
    float2 p4 = __half22float2(c.h);
    xin[0]=p0.x; xin[1]=p0.y; xin[2]=p1.x; xin[3]=p1.y; xin[4]=p2.x;
    xin[5]=p2.y; xin[6]=p3.x; xin[7]=p3.y; xin[8]=p4.x; xin[9]=p4.y;
}

#define BUFA(t) bufA[(t)*EPB + e]
#define BUFB(t) bufB[(t)*EPB + e]
#define BUFC(t) bufC[(t)*EPB + e]

__global__ void __launch_bounds__(BLOCK, 4)
gru_kernel(const float* __restrict__ x,
           const float* __restrict__ wih0, const float* __restrict__ whh0,
           const float* __restrict__ bih0, const float* __restrict__ bhh0,
           const float* __restrict__ wihU, const float* __restrict__ whhU,
           const float* __restrict__ bihU, const float* __restrict__ bhhU,
           float* __restrict__ out)
{
    extern __shared__ float smem[];
    float* sw   = smem;                                   // [2432]
    u64*   bufA = (u64*)(smem + WTOT);                    // [T*EPB] (f0..f3)
    u64*   bufB = bufA + TSTEPS*EPB;                      // [T*EPB] (f4,b0,b1,b2)
    u32*   bufC = (u32*)(bufB + TSTEPS*EPB);              // [T*EPB] (b3,b4)
    const int tid  = threadIdx.x;
    const int side = tid & 1;
    const int e    = tid >> 1;
    const int sideOff = side * 8;

    // ---- cooperative weight prep: pair-split slot layout, pre-scale, merge biases ----
    for (int c = 0; c < 10; ++c) {
        int l = c >> 1, d = c & 1;
        int D = l ? 10 : 1;
        float* w = sw + comboOff(c);
        for (int i = tid; i < 16*D; i += BLOCK) {           // wihT[k][slot]
            int k = i >> 4, s = i & 15;
            float v = 0.f;
            if (s < 15) {
                int  j  = slot2j(s);
                float sc = slot_rz(s) ? 0.5f : 1.0f;
                v = sc * (l == 0 ? wih0[d*15 + j]
                                 : wihU[(((l-1)*2 + d)*15 + j)*10 + k]);
            }
            w[i] = v;
        }
        float* wh = w + 16*D;
        for (int i = tid; i < 80; i += BLOCK) {             // whhT[k][slot]
            int k = i >> 4, s = i & 15;
            float v = 0.f;
            if (s < 15) {
                int  j  = slot2j(s);
                float sc = slot_rz(s) ? 0.5f : 1.0f;
                v = sc * (l == 0 ? whh0[(d*15 + j)*5 + k]
                                 : whhU[(((l-1)*2 + d)*15 + j)*5 + k]);
            }
            wh[i] = v;
        }
        float* bg = wh + 80;                                // gi-side bias
        for (int s = tid; s < 16; s += BLOCK) {
            float v = 0.f;
            if (s < 15) {
                int  j  = slot2j(s);
                float bi = l == 0 ? bih0[d*15 + j] : bihU[((l-1)*2 + d)*15 + j];
                float bh = l == 0 ? bhh0[d*15 + j] : bhhU[((l-1)*2 + d)*15 + j];
                v = slot_rz(s) ? 0.5f*(bi + bh) : bi;
            }
            bg[s] = v;
        }
        float* bh2 = bg + 16;                               // gh-side bias (n slots only)
        for (int s = tid; s < 16; s += BLOCK) {
            float v = 0.f;
            if (s < 15 && !slot_rz(s)) {
                int j = slot2j(s);
                v = l == 0 ? bhh0[d*15 + j] : bhhU[((l-1)*2 + d)*15 + j];
            }
            bh2[s] = v;
        }
    }
    __syncthreads();
    // entries are pair-private from here (in-warp program order covers pair hazards)

    const int b = blockIdx.x * EPB + e;
    const float* xrow = x + (size_t)b * TSTEPS;

    u64 whhr[20], bA[4], bH[4];
    float h[5];
    u64 fscrA[TSTEPS];        // local (side0 only): fwd (f0..f3) fp16
    u32 fscrC[TSTEPS];        // local (side0 only): fwd (f4,pad) fp16

    // ===== layer 0 (D=1): fwd -> fscr, bwd -> merged entries =====
    {
        const float* w = sw + comboOff(0);
        load_dir(w, 1, sideOff, whhr, bA, bH);
#pragma unroll
        for (int u = 0; u < 5; ++u) h[u] = 0.f;
#pragma unroll 1
        for (int t = 0; t < TSTEPS; ++t) {
            float xin[1] = { xrow[t] };
            step_pair<1>(w, sideOff, side, whhr, bA, bH, xin, h);
            if (!side) {
                fscrA[t] = h4pack(__floats2half2_rn(h[0], h[1]), __floats2half2_rn(h[2], h[3]));
                fscrC[t] = h2pack(h[4], 0.f);
            }
        }
    }
    {
        const float* w = sw + comboOff(1);
        load_dir(w, 1, sideOff, whhr, bA, bH);
#pragma unroll
        for (int u = 0; u < 5; ++u) h[u] = 0.f;
#pragma unroll 1
        for (int tt = 0; tt < TSTEPS; ++tt) {
            int t = TSTEPS-1-tt;
            float xin[1] = { xrow[t] };
            step_pair<1>(w, sideOff, side, whhr, bA, bH, xin, h);
            if (!side) {
                u64 fa = fscrA[t]; H2 fc; fc.u = fscrC[t];
                __half2 d0 = __floats2half2_rn(h[0], h[1]);
                __half2 d1 = __floats2half2_rn(h[2], h[3]);
                __half2 d2 = __floats2half2_rn(h[4], 0.f);
                BUFA(t) = fa;
                BUFB(t) = h4pack(__halves2half2(__low2half(fc.h), __low2half(d0)),
                                 __halves2half2(__high2half(d0), __low2half(d1)));
                H2 oc; oc.h = __halves2half2(__high2half(d1), __low2half(d2));
                BUFC(t) = oc.u;
            }
        }
    }

    // ===== layers 1..3: fwd stages into fscr, bwd overwrites entries in place =====
#pragma unroll 1
    for (int l = 1; l < 4; ++l) {
        {   // fwd
            const float* w = sw + comboOff(2*l);
            load_dir(w, 10, sideOff, whhr, bA, bH);
#pragma unroll
            for (int u = 0; u < 5; ++u) h[u] = 0.f;
#pragma unroll 1
            for (int t = 0; t < TSTEPS; ++t) {
                float xin[10];
                cvt_in(BUFA(t), BUFB(t), BUFC(t), xin);
                step_pair<10>(w, sideOff, side, whhr, bA, bH, xin, h);
                if (!side) {
                    fscrA[t] = h4pack(__floats2half2_rn(h[0], h[1]), __floats2half2_rn(h[2], h[3]));
                    fscrC[t] = h2pack(h[4], 0.f);
                }
            }
        }
        {   // bwd
            const float* w = sw + comboOff(2*l+1);
            load_dir(w, 10, sideOff, whhr, bA, bH);
#pragma unroll
            for (int u = 0; u < 5; ++u) h[u] = 0.f;
#pragma unroll 1
            for (int tt = 0; tt < TSTEPS; ++tt) {
                int t = TSTEPS-1-tt;
                float xin[10];
                cvt_in(BUFA(t), BUFB(t), BUFC(t), xin);
                step_pair<10>(w, sideOff, side, whhr, bA, bH, xin, h);
                if (!side) {
                    u64 fa = fscrA[t]; H2 fc; fc.u = fscrC[t];
                    __half2 d0 = __floats2half2_rn(h[0], h[1]);
                    __half2 d1 = __floats2half2_rn(h[2], h[3]);
                    __half2 d2 = __floats2half2_rn(h[4], 0.f);
                    BUFA(t) = fa;
                    BUFB(t) = h4pack(__halves2half2(__low2half(fc.h), __low2half(d0)),
                                     __halves2half2(__high2half(d0), __low2half(d1)));
                    H2 oc; oc.h = __halves2half2(__high2half(d1), __low2half(d2));
                    BUFC(t) = oc.u;
                }
            }
        }
    }

    // ===== layer 4: fwd full (keep final h only); bwd = ONE step at t=T-1 =====
    float hf[5];
    {
        const float* w = sw + comboOff(8);
        load_dir(w, 10, sideOff, whhr, bA, bH);
#pragma unroll
        for (int u = 0; u < 5; ++u) h[u] = 0.f;
#pragma unroll 1
        for (int t = 0; t < TSTEPS; ++t) {
            float xin[10];
            cvt_in(BUFA(t), BUFB(t), BUFC(t), xin);
            step_pair<10>(w, sideOff, side, whhr, bA, bH, xin, h);
        }
#pragma unroll
        for (int u = 0; u < 5; ++u) hf[u] = h[u];
    }
    {
        const float* w = sw + comboOff(9);
        load_dir(w, 10, sideOff, whhr, bA, bH);
#pragma unroll
        for (int u = 0; u < 5; ++u) h[u] = 0.f;
        float xin[10];
        int t = TSTEPS-1;
        cvt_in(BUFA(t), BUFB(t), BUFC(t), xin);
        step_pair<10>(w, sideOff, side, whhr, bA, bH, xin, h);
    }

    if (!side) {
        float2* o2 = (float2*)(out + (size_t)b*10);
        o2[0] = make_float2(hf[0], hf[1]);
        o2[1] = make_float2(hf[2], hf[3]);
        o2[2] = make_float2(hf[4], h[0]);
        o2[3] = make_float2(h[1],  h[2]);
        o2[4] = make_float2(h[3],  h[4]);
    }
}

extern "C" void kernel_launch(void* const* d_in, const int* in_sizes, int n_in,
                              void* d_out, int out_size)
{
    (void)in_sizes; (void)n_in; (void)out_size;
    // 9728 (weights) + 30*64*20 (entries) = 48128 B -> 4 blocks/SM, 16 warps/SM
    const size_t smem = (size_t)WTOT*4 + (size_t)TSTEPS*EPB*(8+8+4);
    cudaFuncSetAttribute(gru_kernel, cudaFuncAttributeMaxDynamicSharedMemorySize, (int)smem);
    gru_kernel<<<NBATCH/EPB, BLOCK, smem>>>(
        (const float*)d_in[0],
        (const float*)d_in[1], (const float*)d_in[2],
        (const float*)d_in[3], (const float*)d_in[4],
        (const float*)d_in[5], (const float*)d_in[6],
        (const float*)d_in[7], (const float*)d_in[8],
        (float*)d_out);
}

// round 16
// speedup vs baseline: 1.5406x; 1.5406x over previous
#include <cuda_runtime.h>
#include <cuda_fp16.h>

#define TSTEPS 30
#define BLOCK  64
#define NBATCH 262144

constexpr int WTOT = 2432;                       // prepped weight floats in smem

typedef unsigned long long u64;
typedef unsigned int       u32;

// ---------- packed fp32x2 helpers (sm_103a FFMA2 path) ----------
__device__ __forceinline__ u64 ffma2(u64 a, u64 b, u64 c) {
    u64 d; asm("fma.rn.f32x2 %0, %1, %2, %3;" : "=l"(d) : "l"(a), "l"(b), "l"(c)); return d;
}
__device__ __forceinline__ u64 splat2(float v) {
    u64 d; asm("mov.b64 %0, {%1, %1};" : "=l"(d) : "f"(v)); return d;
}
__device__ __forceinline__ u64 pack2(float x, float y) {
    u64 d; asm("mov.b64 %0, {%1, %2};" : "=l"(d) : "f"(x), "f"(y)); return d;
}
__device__ __forceinline__ float2 unpack2(u64 v) {
    float2 r; asm("mov.b64 {%0, %1}, %2;" : "=f"(r.x), "=f"(r.y) : "l"(v)); return r;
}
__device__ __forceinline__ float tanhfast(float x){ float r; asm("tanh.approx.f32 %0, %1;" : "=f"(r) : "f"(x)); return r; }

__device__ __forceinline__ int comboOff(int c){ return c < 2 ? c*128 : 256 + (c-2)*272; }

union H4 { u64 u; u32 w[2]; __half2 h[2]; };
union H2 { u32 u; __half2 h; };
__device__ __forceinline__ u64 h4pack(__half2 a, __half2 b){ H4 t; t.h[0]=a; t.h[1]=b; return t.u; }
__device__ __forceinline__ u32 h2pack(float x, float y){ H2 t; t.h = __floats2half2_rn(x,y); return t.u; }

// Slot order (rz-merged): s=2u+g, g in {r,z}, unit u (s<10); s=10..14 n-gate; s=15 pad.
// r/z rows scaled 0.5 (gi+gh merged): sig(v)=0.5+0.5*tanh(v/2); n rows unscaled.

// ---------- one GRU timestep for TWO elements: ALL weights/biases streamed from
// smem (broadcast LDS.128, shared by both elements); no large register arrays ----------
template<int D>
__device__ __forceinline__ void gru_step2(const float* __restrict__ wbase,
                                          const float* xin0, const float* xin1,
                                          float* h0, float* h1)
{
    const float4* wih4 = (const float4*)wbase;
    const float4* whh4 = (const float4*)(wbase + 16*D);
    const float4* bg4  = (const float4*)(wbase + 16*D + 80);
    const float4* bh4  = (const float4*)(wbase + 16*D + 96);
    u64 A0[5], Gn0[3], Hn0[3], A1[5], Gn1[3], Hn1[3];
    {   // accumulator init from smem biases (shared loads)
        float4 c0 = bg4[0], c1 = bg4[1], c2 = bg4[2], c3 = bg4[3];
        u64 b0 = pack2(c0.x,c0.y), b1 = pack2(c0.z,c0.w);
        u64 b2 = pack2(c1.x,c1.y), b3 = pack2(c1.z,c1.w);
        u64 b4 = pack2(c2.x,c2.y);
        u64 g0 = pack2(c2.z,c2.w), g1 = pack2(c3.x,c3.y), g2 = pack2(c3.z,c3.w);
        A0[0]=b0; A1[0]=b0; A0[1]=b1; A1[1]=b1; A0[2]=b2; A1[2]=b2;
        A0[3]=b3; A1[3]=b3; A0[4]=b4; A1[4]=b4;
        Gn0[0]=g0; Gn1[0]=g0; Gn0[1]=g1; Gn1[1]=g1; Gn0[2]=g2; Gn1[2]=g2;
        float4 d2 = bh4[2], d3 = bh4[3];
        u64 e0 = pack2(d2.z,d2.w), e1 = pack2(d3.x,d3.y), e2 = pack2(d3.z,d3.w);
        Hn0[0]=e0; Hn1[0]=e0; Hn0[1]=e1; Hn1[1]=e1; Hn0[2]=e2; Hn1[2]=e2;
    }
#pragma unroll
    for (int k = 0; k < D; ++k) {                 // gi GEMV: ONE weight load, TWO elems
        u64 xs0 = splat2(xin0[k]);
        u64 xs1 = splat2(xin1[k]);
        float4 w0 = wih4[k*4+0], w1 = wih4[k*4+1], w2 = wih4[k*4+2], w3 = wih4[k*4+3];
        u64 p0 = pack2(w0.x,w0.y), p1 = pack2(w0.z,w0.w);
        u64 p2 = pack2(w1.x,w1.y), p3 = pack2(w1.z,w1.w);
        u64 p4 = pack2(w2.x,w2.y), p5 = pack2(w2.z,w2.w);
        u64 p6 = pack2(w3.x,w3.y), p7 = pack2(w3.z,w3.w);
        A0[0]  = ffma2(p0, xs0, A0[0]);   A1[0]  = ffma2(p0, xs1, A1[0]);
        A0[1]  = ffma2(p1, xs0, A0[1]);   A1[1]  = ffma2(p1, xs1, A1[1]);
        A0[2]  = ffma2(p2, xs0, A0[2]);   A1[2]  = ffma2(p2, xs1, A1[2]);
        A0[3]  = ffma2(p3, xs0, A0[3]);   A1[3]  = ffma2(p3, xs1, A1[3]);
        A0[4]  = ffma2(p4, xs0, A0[4]);   A1[4]  = ffma2(p4, xs1, A1[4]);
        Gn0[0] = ffma2(p5, xs0, Gn0[0]);  Gn1[0] = ffma2(p5, xs1, Gn1[0]);
        Gn0[1] = ffma2(p6, xs0, Gn0[1]);  Gn1[1] = ffma2(p6, xs1, Gn1[1]);
        Gn0[2] = ffma2(p7, xs0, Gn0[2]);  Gn1[2] = ffma2(p7, xs1, Gn1[2]);
    }
#pragma unroll
    for (int k = 0; k < 5; ++k) {                 // gh GEMV: streamed whh, TWO elems
        u64 hs0 = splat2(h0[k]);
        u64 hs1 = splat2(h1[k]);
        float4 w0 = whh4[k*4+0], w1 = whh4[k*4+1], w2 = whh4[k*4+2], w3 = whh4[k*4+3];
        u64 p0 = pack2(w0.x,w0.y), p1 = pack2(w0.z,w0.w);
        u64 p2 = pack2(w1.x,w1.y), p3 = pack2(w1.z,w1.w);
        u64 p4 = pack2(w2.x,w2.y), p5 = pack2(w2.z,w2.w);
        u64 p6 = pack2(w3.x,w3.y), p7 = pack2(w3.z,w3.w);
        A0[0]  = ffma2(p0, hs0, A0[0]);   A1[0]  = ffma2(p0, hs1, A1[0]);
        A0[1]  = ffma2(p1, hs0, A0[1]);   A1[1]  = ffma2(p1, hs1, A1[1]);
        A0[2]  = ffma2(p2, hs0, A0[2]);   A1[2]  = ffma2(p2, hs1, A1[2]);
        A0[3]  = ffma2(p3, hs0, A0[3]);   A1[3]  = ffma2(p3, hs1, A1[3]);
        A0[4]  = ffma2(p4, hs0, A0[4]);   A1[4]  = ffma2(p4, hs1, A1[4]);
        Hn0[0] = ffma2(p5, hs0, Hn0[0]);  Hn1[0] = ffma2(p5, hs1, Hn1[0]);
        Hn0[1] = ffma2(p6, hs0, Hn0[1]);  Hn1[1] = ffma2(p6, hs1, Hn1[1]);
        Hn0[2] = ffma2(p7, hs0, Hn0[2]);  Hn1[2] = ffma2(p7, hs1, Hn1[2]);
    }
    float gn0[6], hn0[6], gn1[6], hn1[6];
#pragma unroll
    for (int p = 0; p < 3; ++p) {
        float2 a = unpack2(Gn0[p]); gn0[2*p] = a.x; gn0[2*p+1] = a.y;
        float2 c = unpack2(Hn0[p]); hn0[2*p] = c.x; hn0[2*p+1] = c.y;
        float2 e = unpack2(Gn1[p]); gn1[2*p] = e.x; gn1[2*p+1] = e.y;
        float2 f = unpack2(Hn1[p]); hn1[2*p] = f.x; hn1[2*p+1] = f.y;
    }
#pragma unroll
    for (int u = 0; u < 5; ++u) {
        float2 rz0 = unpack2(A0[u]);
        float2 rz1 = unpack2(A1[u]);
        float r0 = fmaf(0.5f, tanhfast(rz0.x), 0.5f);
        float r1 = fmaf(0.5f, tanhfast(rz1.x), 0.5f);
        float z0 = fmaf(0.5f, tanhfast(rz0.y), 0.5f);
        float z1 = fmaf(0.5f, tanhfast(rz1.y), 0.5f);
        float n0 = tanhfast(fmaf(r0, hn0[u], gn0[u]));
        float n1 = tanhfast(fmaf(r1, hn1[u], gn1[u]));
        h0[u] = fmaf(z0, h0[u] - n0, n0);
        h1[u] = fmaf(z1, h1[u] - n1, n1);
    }
}

// fp16 triplet -> 10 floats (fwd 0..4, bwd 5..9)
__device__ __forceinline__ void cvt_in(u64 ra, u64 rb, u32 rc, float* xin)
{
    H4 a, b; H2 c; a.u = ra; b.u = rb; c.u = rc;
    float2 p0 = __half22float2(a.h[0]);
    float2 p1 = __half22float2(a.h[1]);
    float2 p2 = __half22float2(b.h[0]);
    float2 p3 = __half22float2(b.h[1]);
    float2 p4 = __half22float2(c.h);
    xin[0]=p0.x; xin[1]=p0.y; xin[2]=p1.x; xin[3]=p1.y; xin[4]=p2.x;
    xin[5]=p2.y; xin[6]=p3.x; xin[7]=p3.y; xin[8]=p4.x; xin[9]=p4.y;
}

// pack merged entry: fwd-staged (fa = f0..f3, fcu = {f4,_}) + bwd h
__device__ __forceinline__ void pack_entry(const float* hb, u64 fa, u32 fcu,
                                           u64& oa, u64& ob, u32& oc)
{
    H2 fc; fc.u = fcu;
    __half2 d0 = __floats2half2_rn(hb[0], hb[1]);
    __half2 d1 = __floats2half2_rn(hb[2], hb[3]);
    __half2 d2 = __floats2half2_rn(hb[4], 0.f);
    oa = fa;
    ob = h4pack(__halves2half2(__low2half(fc.h), __low2half(d0)),
                __halves2half2(__high2half(d0), __low2half(d1)));
    H2 t; t.h = __halves2half2(__high2half(d1), __low2half(d2));
    oc = t.u;
}

__global__ void __launch_bounds__(BLOCK, 4)
gru_kernel(const float* __restrict__ x,
           const float* __restrict__ wih0, const float* __restrict__ whh0,
           const float* __restrict__ bih0, const float* __restrict__ bhh0,
           const float* __restrict__ wihU, const float* __restrict__ whhU,
           const float* __restrict__ bihU, const float* __restrict__ bhhU,
           float* __restrict__ out)
{
    extern __shared__ float smem[];
    float* sw   = smem;                                   // [2432]
    u64*   bufA = (u64*)(smem + WTOT);                    // [T*BLOCK] elem0 (f0..f3)
    u64*   bufB = bufA + TSTEPS*BLOCK;                    // [T*BLOCK] elem0 (f4,b0,b1,b2)
    u32*   bufC = (u32*)(bufB + TSTEPS*BLOCK);            // [T*BLOCK] elem0 (b3,b4)
    const int tid = threadIdx.x;

    // ---- cooperative weight prep: transpose to slot layout, pre-scale, merge biases ----
    for (int c = 0; c < 10; ++c) {
        int l = c >> 1, d = c & 1;
        int D = l ? 10 : 1;
        float* w = sw + comboOff(c);
        for (int i = tid; i < 16*D; i += BLOCK) {           // wihT[k][slot]
            int k = i >> 4, s = i & 15;
            float v = 0.f;
            if (s < 15) {
                int  j  = (s < 10) ? ((s & 1)*5 + (s >> 1)) : s;
                float sc = (s < 10) ? 0.5f : 1.0f;
                v = sc * (l == 0 ? wih0[d*15 + j]
                                 : wihU[(((l-1)*2 + d)*15 + j)*10 + k]);
            }
            w[i] = v;
        }
        float* wh = w + 16*D;
        for (int i = tid; i < 80; i += BLOCK) {             // whhT[k][slot]
            int k = i >> 4, s = i & 15;
            float v = 0.f;
            if (s < 15) {
                int  j  = (s < 10) ? ((s & 1)*5 + (s >> 1)) : s;
                float sc = (s < 10) ? 0.5f : 1.0f;
                v = sc * (l == 0 ? whh0[(d*15 + j)*5 + k]
                                 : whhU[(((l-1)*2 + d)*15 + j)*5 + k]);
            }
            wh[i] = v;
        }
        float* bg = wh + 80;                                // gi-side bias
        for (int s = tid; s < 16; s += BLOCK) {
            float v = 0.f;
            if (s < 15) {
                int  j  = (s < 10) ? ((s & 1)*5 + (s >> 1)) : s;
                float sc = (s < 10) ? 0.5f : 1.0f;
                float bi = l == 0 ? bih0[d*15 + j] : bihU[((l-1)*2 + d)*15 + j];
                float bh = l == 0 ? bhh0[d*15 + j] : bhhU[((l-1)*2 + d)*15 + j];
                v = sc * (s < 10 ? (bi + bh) : bi);
            }
            bg[s] = v;
        }
        float* bh2 = bg + 16;                               // gh-side n bias
        for (int s = tid; s < 16; s += BLOCK) {
            float v = 0.f;
            if (s >= 10 && s < 15)
                v = l == 0 ? bhh0[d*15 + s] : bhhU[((l-1)*2 + d)*15 + s];
            bh2[s] = v;
        }
    }
    __syncthreads();
    // smem buf slots are thread-private from here on; no further syncs needed

    const int b0 = blockIdx.x * (2*BLOCK) + tid;   // element 0 (smem buffer)
    const int b1 = b0 + BLOCK;                     // element 1 (local buffer)
    const float* xrow0 = x + (size_t)b0 * TSTEPS;
    const float* xrow1 = x + (size_t)b1 * TSTEPS;

    float h0[5], h1[5];

    // elem1 activation buffer in local memory (entry t at index t+1; pads both ends)
    u64 lbufA[TSTEPS+2], lbufB[TSTEPS+2];
    u32 lbufC[TSTEPS+2];
    // fwd staging (local, latency-covered by early loads)
    u64 fscrA0[TSTEPS], fscrA1[TSTEPS];
    u32 fscrC0[TSTEPS], fscrC1[TSTEPS];

    // ===== layer 0 (D=1): fwd -> fscr, bwd -> merged entries =====
    {
        const float* w = sw + comboOff(0);
#pragma unroll
        for (int u = 0; u < 5; ++u) { h0[u] = 0.f; h1[u] = 0.f; }
#pragma unroll 1
        for (int t = 0; t < TSTEPS; ++t) {
            float xin0[1] = { xrow0[t] };
            float xin1[1] = { xrow1[t] };
            gru_step2<1>(w, xin0, xin1, h0, h1);
            fscrA0[t] = h4pack(__floats2half2_rn(h0[0], h0[1]), __floats2half2_rn(h0[2], h0[3]));
            fscrA1[t] = h4pack(__floats2half2_rn(h1[0], h1[1]), __floats2half2_rn(h1[2], h1[3]));
            fscrC0[t] = h2pack(h0[4], 0.f);
            fscrC1[t] = h2pack(h1[4], 0.f);
        }
    }
    {
        const float* w = sw + comboOff(1);
#pragma unroll
        for (int u = 0; u < 5; ++u) { h0[u] = 0.f; h1[u] = 0.f; }
#pragma unroll 1
        for (int tt = 0; tt < TSTEPS; ++tt) {
            int t = TSTEPS-1-tt;
            u64 fa0 = fscrA0[t]; u32 fc0 = fscrC0[t];
            u64 fa1 = fscrA1[t]; u32 fc1 = fscrC1[t];
            float xin0[1] = { xrow0[t] };
            float xin1[1] = { xrow1[t] };
            gru_step2<1>(w, xin0, xin1, h0, h1);
            u64 oa, ob; u32 oc;
            pack_entry(h0, fa0, fc0, oa, ob, oc);
            bufA[t*BLOCK+tid] = oa; bufB[t*BLOCK+tid] = ob; bufC[t*BLOCK+tid] = oc;
            pack_entry(h1, fa1, fc1, oa, ob, oc);
            lbufA[t+1] = oa; lbufB[t+1] = ob; lbufC[t+1] = oc;
        }
    }

    // ===== layers 1..3: fwd -> fscr, bwd overwrites buffers in place =====
#pragma unroll 1
    for (int l = 1; l < 4; ++l) {
        {   // fwd: elem1 input prefetched one step ahead
            const float* w = sw + comboOff(2*l);
#pragma unroll
            for (int u = 0; u < 5; ++u) { h0[u] = 0.f; h1[u] = 0.f; }
            u64 ra = lbufA[1], rb = lbufB[1]; u32 rc = lbufC[1];
#pragma unroll 1
            for (int t = 0; t < TSTEPS; ++t) {
                u64 ca = ra, cb = rb; u32 cc = rc;
                ra = lbufA[t+2]; rb = lbufB[t+2]; rc = lbufC[t+2];  // pad at 31
                float xin0[10], xin1[10];
                cvt_in(bufA[t*BLOCK+tid], bufB[t*BLOCK+tid], bufC[t*BLOCK+tid], xin0);
                cvt_in(ca, cb, cc, xin1);
                gru_step2<10>(w, xin0, xin1, h0, h1);
                fscrA0[t] = h4pack(__floats2half2_rn(h0[0], h0[1]), __floats2half2_rn(h0[2], h0[3]));
                fscrA1[t] = h4pack(__floats2half2_rn(h1[0], h1[1]), __floats2half2_rn(h1[2], h1[3]));
                fscrC0[t] = h2pack(h0[4], 0.f);
                fscrC1[t] = h2pack(h1[4], 0.f);
            }
        }
        {   // bwd: elem1 input prefetched one step ahead (downward)
            const float* w = sw + comboOff(2*l+1);
#pragma unroll
            for (int u = 0; u < 5; ++u) { h0[u] = 0.f; h1[u] = 0.f; }
            u64 ra = lbufA[TSTEPS], rb = lbufB[TSTEPS]; u32 rc = lbufC[TSTEPS];
#pragma unroll 1
            for (int tt = 0; tt < TSTEPS; ++tt) {
                int t = TSTEPS-1-tt;
                u64 ca = ra, cb = rb; u32 cc = rc;
                ra = lbufA[t]; rb = lbufB[t]; rc = lbufC[t];        // pad at 0
                u64 fa0 = fscrA0[t]; u32 fc0 = fscrC0[t];
                u64 fa1 = fscrA1[t]; u32 fc1 = fscrC1[t];
                float xin0[10], xin1[10];
                cvt_in(bufA[t*BLOCK+tid], bufB[t*BLOCK+tid], bufC[t*BLOCK+tid], xin0);
                cvt_in(ca, cb, cc, xin1);
                gru_step2<10>(w, xin0, xin1, h0, h1);
                u64 oa, ob; u32 oc;
                pack_entry(h0, fa0, fc0, oa, ob, oc);
                bufA[t*BLOCK+tid] = oa; bufB[t*BLOCK+tid] = ob; bufC[t*BLOCK+tid] = oc;
                pack_entry(h1, fa1, fc1, oa, ob, oc);
                lbufA[t+1] = oa; lbufB[t+1] = ob; lbufC[t+1] = oc;
            }
        }
    }

    // ===== layer 4: fwd full (keep final h only); bwd = ONE step at t=T-1 =====
    float hf0[5], hf1[5];
    {
        const float* w = sw + comboOff(8);
#pragma unroll
        for (int u = 0; u < 5; ++u) { h0[u] = 0.f; h1[u] = 0.f; }
        u64 ra = lbufA[1], rb = lbufB[1]; u32 rc = lbufC[1];
#pragma unroll 1
        for (int t = 0; t < TSTEPS; ++t) {
            u64 ca = ra, cb = rb; u32 cc = rc;
            ra = lbufA[t+2]; rb = lbufB[t+2]; rc = lbufC[t+2];
            float xin0[10], xin1[10];
            cvt_in(bufA[t*BLOCK+tid], bufB[t*BLOCK+tid], bufC[t*BLOCK+tid], xin0);
            cvt_in(ca, cb, cc, xin1);
            gru_step2<10>(w, xin0, xin1, h0, h1);
        }
#pragma unroll
        for (int u = 0; u < 5; ++u) { hf0[u] = h0[u]; hf1[u] = h1[u]; }
    }
    {
        const float* w = sw + comboOff(9);
#pragma unroll
        for (int u = 0; u < 5; ++u) { h0[u] = 0.f; h1[u] = 0.f; }
        int t = TSTEPS-1;
        float xin0[10], xin1[10];
        cvt_in(bufA[t*BLOCK+tid], bufB[t*BLOCK+tid], bufC[t*BLOCK+tid], xin0);
        cvt_in(lbufA[t+1], lbufB[t+1], lbufC[t+1], xin1);
        gru_step2<10>(w, xin0, xin1, h0, h1);
    }

    float2* o0 = (float2*)(out + (size_t)b0*10);
    o0[0] = make_float2(hf0[0], hf0[1]);
    o0[1] = make_float2(hf0[2], hf0[3]);
    o0[2] = make_float2(hf0[4], h0[0]);
    o0[3] = make_float2(h0[1],  h0[2]);
    o0[4] = make_float2(h0[3],  h0[4]);
    float2* o1 = (float2*)(out + (size_t)b1*10);
    o1[0] = make_float2(hf1[0], hf1[1]);
    o1[1] = make_float2(hf1[2], hf1[3]);
    o1[2] = make_float2(hf1[4], h1[0]);
    o1[3] = make_float2(h1[1],  h1[2]);
    o1[4] = make_float2(h1[3],  h1[4]);
}

extern "C" void kernel_launch(void* const* d_in, const int* in_sizes, int n_in,
                              void* d_out, int out_size)
{
    (void)in_sizes; (void)n_in; (void)out_size;
    // 9728 (weights) + 30*64*20 (elem0 buffer) = 48128 B -> 4 blocks/SM, 8 warps/SM,
    // 512 elements resident per SM (256 smem-backed + 256 local-backed)
    const size_t smem = (size_t)WTOT*4 + (size_t)TSTEPS*BLOCK*(8+8+4);
    cudaFuncSetAttribute(gru_kernel, cudaFuncAttributeMaxDynamicSharedMemorySize, (int)smem);
    gru_kernel<<<NBATCH/(2*BLOCK), BLOCK, smem>>>(
        (const float*)d_in[0],
        (const float*)d_in[1], (const float*)d_in[2],
        (const float*)d_in[3], (const float*)d_in[4],
        (const float*)d_in[5], (const float*)d_in[6],
        (const float*)d_in[7], (const float*)d_in[8],
        (float*)d_out);
}